// round 1
// baseline (speedup 1.0000x reference)
#include <cuda_runtime.h>
#include <cstdint>
#include <cstddef>

// Problem constants
#define BATCH 4
#define HEADS 16
#define LQ 2048
#define SK 2048
#define DH 64

// Tiling
#define BQ   16      // query rows per CTA
#define SKT  128     // s-tile
#define ES   2052    // padded stride of E tile (floats)  -> (row*2052)%32 banks = 4*row
#define KSS  68      // padded stride of K/V tile (floats)

#define NTHREADS 256
#define NWARPS   8

__device__ __forceinline__ uint32_t f2tf32(float f) {
    uint32_t u;
    asm("cvt.rna.tf32.f32 %0, %1;" : "=r"(u) : "f"(f));
    return u;
}

__device__ __forceinline__ void mma_tf32(float c[4], const uint32_t a[4], const uint32_t b[2]) {
    asm volatile(
        "mma.sync.aligned.m16n8k8.row.col.f32.tf32.tf32.f32 "
        "{%0,%1,%2,%3}, {%4,%5,%6,%7}, {%8,%9}, {%0,%1,%2,%3};"
        : "+f"(c[0]), "+f"(c[1]), "+f"(c[2]), "+f"(c[3])
        : "r"(a[0]), "r"(a[1]), "r"(a[2]), "r"(a[3]),
          "r"(b[0]), "r"(b[1]));
}

__global__ __launch_bounds__(NTHREADS, 1)
void attn_tf32_kernel(const float* __restrict__ q,
                      const float* __restrict__ k,
                      const float* __restrict__ v,
                      float* __restrict__ out) {
    extern __shared__ float sm[];
    float* Es  = sm;                    // [BQ][ES]      unnormalized exp(logits)
    float* Ks  = Es + BQ * ES;          // [SKT][KSS]    K tile, reused for V tile
    float* Qs  = Ks + SKT * KSS;        // [BQ][KSS]
    float* red = Qs + BQ * KSS;         // [16][16] partial row sums
    float* inv = red + 256;             // [16] 1/rowsum

    const int bh  = blockIdx.y;
    const int q0  = blockIdx.x * BQ;

    const float* qp = q + ((size_t)bh * LQ + q0) * DH;
    const float* kp = k + (size_t)bh * SK * DH;
    const float* vp = v + (size_t)bh * SK * DH;
    float* op = out + ((size_t)bh * LQ + q0) * DH;
    float* sp = out + (size_t)BATCH * HEADS * LQ * DH
                    + ((size_t)bh * LQ + q0) * (size_t)SK;

    const int tid  = threadIdx.x;
    const int lane = tid & 31;
    const int warp = tid >> 5;
    const int gr   = lane >> 2;   // group row (0..7)
    const int tg   = lane & 3;    // thread-in-group (0..3)

    // ---- load Q tile (16 x 64) : one float4 per thread ----
    {
        int r = tid >> 4, c4 = tid & 15;
        float4 val = *(const float4*)(qp + (size_t)r * DH + c4 * 4);
        *(float4*)(Qs + r * KSS + c4 * 4) = val;
    }
    __syncthreads();

    // ---- build Q A-fragments (tf32), identical in every warp, resident ----
    uint32_t qa[8][4];
#pragma unroll
    for (int ks = 0; ks < 8; ks++) {
        qa[ks][0] = f2tf32(Qs[gr * KSS + ks * 8 + tg]);
        qa[ks][1] = f2tf32(Qs[(gr + 8) * KSS + ks * 8 + tg]);
        qa[ks][2] = f2tf32(Qs[gr * KSS + ks * 8 + tg + 4]);
        qa[ks][3] = f2tf32(Qs[(gr + 8) * KSS + ks * 8 + tg + 4]);
    }

    const float scale = 0.125f;   // 1/sqrt(64)

    // ==================== Phase 1: E = exp(Q K^T * scale) into SMEM ====================
    for (int s0 = 0; s0 < SK; s0 += SKT) {
        __syncthreads();  // protect Ks from previous iteration's readers
        // load K tile 128x64 (8 float4 per thread), coalesced
#pragma unroll
        for (int i = 0; i < 8; i++) {
            int idx = tid + i * NTHREADS;
            int r = idx >> 4, c4 = idx & 15;
            float4 val = *(const float4*)(kp + (size_t)(s0 + r) * DH + c4 * 4);
            *(float4*)(Ks + r * KSS + c4 * 4) = val;
        }
        __syncthreads();

        const int nb0 = warp * 16;          // 16 s-columns per warp
        float acc0[4] = {0.f, 0.f, 0.f, 0.f};
        float acc1[4] = {0.f, 0.f, 0.f, 0.f};
#pragma unroll
        for (int ks = 0; ks < 8; ks++) {
            uint32_t b0[2], b1[2];
            // B[k][n] = K[s = n][d = k]; rows padded by KSS => conflict-free
            b0[0] = f2tf32(Ks[(nb0 + gr)     * KSS + ks * 8 + tg]);
            b0[1] = f2tf32(Ks[(nb0 + gr)     * KSS + ks * 8 + tg + 4]);
            b1[0] = f2tf32(Ks[(nb0 + 8 + gr) * KSS + ks * 8 + tg]);
            b1[1] = f2tf32(Ks[(nb0 + 8 + gr) * KSS + ks * 8 + tg + 4]);
            mma_tf32(acc0, qa[ks], b0);
            mma_tf32(acc1, qa[ks], b1);
        }
        // exp + store to E tile (each warp owns its 16 columns; no races)
        {
            int colb = s0 + nb0 + 2 * tg;
            Es[gr * ES + colb]           = __expf(acc0[0] * scale);
            Es[gr * ES + colb + 1]       = __expf(acc0[1] * scale);
            Es[(gr + 8) * ES + colb]     = __expf(acc0[2] * scale);
            Es[(gr + 8) * ES + colb + 1] = __expf(acc0[3] * scale);
            int colb2 = colb + 8;
            Es[gr * ES + colb2]           = __expf(acc1[0] * scale);
            Es[gr * ES + colb2 + 1]       = __expf(acc1[1] * scale);
            Es[(gr + 8) * ES + colb2]     = __expf(acc1[2] * scale);
            Es[(gr + 8) * ES + colb2 + 1] = __expf(acc1[3] * scale);
        }
    }
    __syncthreads();

    // ==================== Phase 2: row sums -> 1/sum ====================
    {
        int r = tid >> 4, c = tid & 15;
        float s = 0.f;
#pragma unroll 8
        for (int j = 0; j < SK / 16; j++)
            s += Es[r * ES + c + j * 16];
        red[r * 16 + c] = s;
    }
    __syncthreads();
    if (tid < 16) {
        float s = 0.f;
#pragma unroll
        for (int j = 0; j < 16; j++) s += red[tid * 16 + j];
        inv[tid] = 1.0f / s;
    }
    __syncthreads();

    // ==================== Phase 3: write normalized scores ====================
    {
        // 16*2048 floats = 8192 float4, 32 per thread; coalesced float4 stores
#pragma unroll
        for (int i = 0; i < 32; i++) {
            int idx = tid + i * NTHREADS;     // float4 index
            int r  = idx >> 9;                // 512 float4 per row
            int c4 = idx & 511;
            float4 e = *(float4*)(Es + r * ES + c4 * 4);
            float is = inv[r];
            e.x *= is; e.y *= is; e.z *= is; e.w *= is;
            *(float4*)(sp + (size_t)r * SK + c4 * 4) = e;
        }
    }

    // ==================== Phase 4: O = (E @ V) * (1/sum) ====================
    float oa0[4] = {0.f, 0.f, 0.f, 0.f};
    float oa1[4] = {0.f, 0.f, 0.f, 0.f};
    const int nb0 = warp * 8;   // 8 output columns per warp (8 warps * 8 = 64)

    for (int s0 = 0; s0 < SK; s0 += SKT) {
        __syncthreads();  // protect Ks (V tile) from previous readers
#pragma unroll
        for (int i = 0; i < 8; i++) {
            int idx = tid + i * NTHREADS;
            int r = idx >> 4, c4 = idx & 15;
            float4 val = *(const float4*)(vp + (size_t)(s0 + r) * DH + c4 * 4);
            *(float4*)(Ks + r * KSS + c4 * 4) = val;
        }
        __syncthreads();

#pragma unroll
        for (int ks = 0; ks < 16; ks++) {
            int k0 = ks * 8;
            uint32_t a[4];
            a[0] = f2tf32(Es[gr * ES + s0 + k0 + tg]);
            a[1] = f2tf32(Es[(gr + 8) * ES + s0 + k0 + tg]);
            a[2] = f2tf32(Es[gr * ES + s0 + k0 + tg + 4]);
            a[3] = f2tf32(Es[(gr + 8) * ES + s0 + k0 + tg + 4]);
            uint32_t b[2];
            b[0] = f2tf32(Ks[(k0 + tg)     * KSS + nb0 + gr]);
            b[1] = f2tf32(Ks[(k0 + tg + 4) * KSS + nb0 + gr]);
            if (ks & 1) mma_tf32(oa1, a, b);
            else        mma_tf32(oa0, a, b);
        }
    }

    // write O (divide by row sum here; scores already normalized)
    {
        float is0 = inv[gr], is1 = inv[gr + 8];
        int col = nb0 + 2 * tg;
        op[(size_t)gr * DH + col]           = (oa0[0] + oa1[0]) * is0;
        op[(size_t)gr * DH + col + 1]       = (oa0[1] + oa1[1]) * is0;
        op[(size_t)(gr + 8) * DH + col]     = (oa0[2] + oa1[2]) * is1;
        op[(size_t)(gr + 8) * DH + col + 1] = (oa0[3] + oa1[3]) * is1;
    }
}

extern "C" void kernel_launch(void* const* d_in, const int* in_sizes, int n_in,
                              void* d_out, int out_size) {
    const float* q = (const float*)d_in[0];
    const float* k = (const float*)d_in[1];
    const float* v = (const float*)d_in[2];
    float* out = (float*)d_out;

    // dynamic SMEM: E(16*2052) + K/V(128*68) + Q(16*68) + red(256) + inv(16)
    size_t smem = (size_t)(BQ * ES + SKT * KSS + BQ * KSS + 256 + 16) * sizeof(float);

    static bool configured = false;
    if (!configured) {
        cudaFuncSetAttribute(attn_tf32_kernel,
                             cudaFuncAttributeMaxDynamicSharedMemorySize,
                             (int)smem);
        configured = true;
    }

    dim3 grid(LQ / BQ, BATCH * HEADS);   // (128, 64)
    attn_tf32_kernel<<<grid, NTHREADS, smem>>>(q, k, v, out);
}

// round 3
// speedup vs baseline: 1.1128x; 1.1128x over previous
#include <cuda_runtime.h>
#include <cstdint>
#include <cstddef>

// Problem constants
#define BATCH 4
#define HEADS 16
#define LQ 2048
#define SK 2048
#define DH 64

// Tiling
#define BQ   16      // query rows per CTA
#define SKT  128     // s-tile
#define ES   2052    // padded stride of E tile (floats)
#define KSS  68      // padded stride of K/Q tiles (floats) -> conflict-free QK B-frag loads
#define VSS  72      // padded stride of V tile -> conflict-free transposed B-frag loads
#define OSS  65      // padded stride of O scratch

#define NTHREADS 512
#define NWARPS   16

__device__ __forceinline__ uint32_t f2tf32(float f) {
    uint32_t u;
    asm("cvt.rna.tf32.f32 %0, %1;" : "=r"(u) : "f"(f));
    return u;
}

__device__ __forceinline__ void mma_tf32(float c[4], const uint32_t a[4], const uint32_t b[2]) {
    asm volatile(
        "mma.sync.aligned.m16n8k8.row.col.f32.tf32.tf32.f32 "
        "{%0,%1,%2,%3}, {%4,%5,%6,%7}, {%8,%9}, {%0,%1,%2,%3};"
        : "+f"(c[0]), "+f"(c[1]), "+f"(c[2]), "+f"(c[3])
        : "r"(a[0]), "r"(a[1]), "r"(a[2]), "r"(a[3]),
          "r"(b[0]), "r"(b[1]));
}

__global__ __launch_bounds__(NTHREADS, 1)
void attn_tf32_kernel(const float* __restrict__ q,
                      const float* __restrict__ k,
                      const float* __restrict__ v,
                      float* __restrict__ out) {
    extern __shared__ float sm[];
    float* Es  = sm;                       // [BQ][ES]   unnormalized exp(logits)
    float* Ks  = Es  + BQ * ES;            // [SKT][KSS]
    float* Vs  = Ks  + SKT * KSS;          // [SKT][VSS]
    float* Qs  = Vs  + SKT * VSS;          // [BQ][KSS]
    float* Os  = Qs  + BQ * KSS;           // [16][OSS]  O accumulation scratch
    float* red = Os  + 16 * OSS;           // [16][32]   partial row sums
    float* inv = red + 512;                // [16]

    const int bh  = blockIdx.y;
    const int q0  = blockIdx.x * BQ;

    const float* qp = q + ((size_t)bh * LQ + q0) * DH;
    const float* kp = k + (size_t)bh * SK * DH;
    const float* vp = v + (size_t)bh * SK * DH;
    float* op = out + ((size_t)bh * LQ + q0) * DH;
    float* sp = out + (size_t)BATCH * HEADS * LQ * DH
                    + ((size_t)bh * LQ + q0) * (size_t)SK;

    const int tid  = threadIdx.x;
    const int lane = tid & 31;
    const int warp = tid >> 5;
    const int gr   = lane >> 2;   // group row (0..7)
    const int tg   = lane & 3;    // thread-in-group (0..3)

    // ---- zero O scratch (ALL 16*OSS floats; R2 bug was leaving 1024..1039 garbage) ----
    for (int i = tid; i < 16 * OSS; i += NTHREADS) Os[i] = 0.f;

    // ---- load Q tile (16 x 64) ----
    if (tid < 256) {
        int r = tid >> 4, c4 = tid & 15;
        *(float4*)(Qs + r * KSS + c4 * 4) =
            *(const float4*)(qp + (size_t)r * DH + c4 * 4);
    }
    __syncthreads();

    // ---- Q A-fragments (tf32), identical in every warp, register-resident ----
    uint32_t qa[8][4];
#pragma unroll
    for (int ks = 0; ks < 8; ks++) {
        qa[ks][0] = f2tf32(Qs[gr * KSS + ks * 8 + tg]);
        qa[ks][1] = f2tf32(Qs[(gr + 8) * KSS + ks * 8 + tg]);
        qa[ks][2] = f2tf32(Qs[gr * KSS + ks * 8 + tg + 4]);
        qa[ks][3] = f2tf32(Qs[(gr + 8) * KSS + ks * 8 + tg + 4]);
    }

    const float scale = 0.125f;   // 1/sqrt(64)

    // per-warp O partial accumulators: 16 rows x 64 cols (8 n-chunks of m16n8)
    float o[8][4];
#pragma unroll
    for (int j = 0; j < 8; j++) { o[j][0] = o[j][1] = o[j][2] = o[j][3] = 0.f; }

    const int n0 = warp * 8;   // this warp's 8 s-columns within the tile

    // ==================== Fused pass: E = exp(QK^T*scale); O += E@V ====================
    for (int s0 = 0; s0 < SK; s0 += SKT) {
        __syncthreads();  // protect Ks/Vs from previous iteration readers
        // load K tile 128x64 and V tile 128x64 (4 float4 each per thread), coalesced
#pragma unroll
        for (int i = 0; i < 4; i++) {
            int idx = tid + i * NTHREADS;
            int r = idx >> 4, c4 = idx & 15;
            *(float4*)(Ks + r * KSS + c4 * 4) =
                *(const float4*)(kp + (size_t)(s0 + r) * DH + c4 * 4);
        }
#pragma unroll
        for (int i = 0; i < 4; i++) {
            int idx = tid + i * NTHREADS;
            int r = idx >> 4, c4 = idx & 15;
            *(float4*)(Vs + r * VSS + c4 * 4) =
                *(const float4*)(vp + (size_t)(s0 + r) * DH + c4 * 4);
        }
        __syncthreads();

        // --- QK^T for this warp's 8 columns ---
        float acc[4] = {0.f, 0.f, 0.f, 0.f};
#pragma unroll
        for (int ks = 0; ks < 8; ks++) {
            uint32_t b[2];
            b[0] = f2tf32(Ks[(n0 + gr) * KSS + ks * 8 + tg]);
            b[1] = f2tf32(Ks[(n0 + gr) * KSS + ks * 8 + tg + 4]);
            mma_tf32(acc, qa[ks], b);
        }

        // --- exp + store to E tile (warp-private columns) ---
        float e0 = __expf(acc[0] * scale);
        float e1 = __expf(acc[1] * scale);
        float e2 = __expf(acc[2] * scale);
        float e3 = __expf(acc[3] * scale);
        {
            int colb = s0 + n0 + 2 * tg;
            *(float2*)(Es + gr * ES + colb)       = make_float2(e0, e1);
            *(float2*)(Es + (gr + 8) * ES + colb) = make_float2(e2, e3);
        }
        __syncwarp();

        // --- read back own columns as A fragment (k=8 chunk) ---
        uint32_t a[4];
        a[0] = f2tf32(Es[gr * ES + s0 + n0 + tg]);
        a[1] = f2tf32(Es[(gr + 8) * ES + s0 + n0 + tg]);
        a[2] = f2tf32(Es[gr * ES + s0 + n0 + tg + 4]);
        a[3] = f2tf32(Es[(gr + 8) * ES + s0 + n0 + tg + 4]);

        // --- O += E_chunk @ V_chunk  (m16 k8 n64, warp's 8 V rows) ---
        const int vr = warp * 8;
#pragma unroll
        for (int j = 0; j < 8; j++) {
            uint32_t b[2];
            b[0] = f2tf32(Vs[(vr + tg) * VSS + j * 8 + gr]);
            b[1] = f2tf32(Vs[(vr + tg + 4) * VSS + j * 8 + gr]);
            mma_tf32(o[j], a, b);
        }
    }

    // ==================== Reduce O partials across warps (SMEM atomics) ====================
#pragma unroll
    for (int j = 0; j < 8; j++) {
        int c = j * 8 + 2 * tg;
        atomicAdd(&Os[gr * OSS + c],           o[j][0]);
        atomicAdd(&Os[gr * OSS + c + 1],       o[j][1]);
        atomicAdd(&Os[(gr + 8) * OSS + c],     o[j][2]);
        atomicAdd(&Os[(gr + 8) * OSS + c + 1], o[j][3]);
    }
    __syncthreads();

    // ==================== Row sums -> 1/sum ====================
    {
        int r = tid >> 5, c = tid & 31;
        float s = 0.f;
#pragma unroll 8
        for (int j = 0; j < SK / 32; j++)
            s += Es[r * ES + c + j * 32];
        red[r * 32 + c] = s;
    }
    __syncthreads();
    if (tid < 16) {
        float s = 0.f;
#pragma unroll
        for (int j = 0; j < 32; j++) s += red[tid * 32 + j];
        inv[tid] = 1.0f / s;
    }
    __syncthreads();

    // ==================== Write normalized scores ====================
    {
        // 16*2048 floats = 8192 float4, 16 per thread; coalesced float4 stores
#pragma unroll
        for (int i = 0; i < 16; i++) {
            int idx = tid + i * NTHREADS;     // float4 index
            int r  = idx >> 9;                // 512 float4 per row
            int c4 = idx & 511;
            float4 e = *(float4*)(Es + r * ES + c4 * 4);
            float is = inv[r];
            e.x *= is; e.y *= is; e.z *= is; e.w *= is;
            *(float4*)(sp + (size_t)r * SK + c4 * 4) = e;
        }
    }

    // ==================== Write O ====================
    {
#pragma unroll
        for (int i = 0; i < 2; i++) {
            int idx = tid + i * NTHREADS;     // 0..1023
            int r = idx >> 6, c = idx & 63;
            op[(size_t)r * DH + c] = Os[r * OSS + c] * inv[r];
        }
    }
}

extern "C" void kernel_launch(void* const* d_in, const int* in_sizes, int n_in,
                              void* d_out, int out_size) {
    const float* q = (const float*)d_in[0];
    const float* k = (const float*)d_in[1];
    const float* v = (const float*)d_in[2];
    float* out = (float*)d_out;

    // dynamic SMEM (floats): E + K + V + Q + Os + red + inv
    size_t smem = (size_t)(BQ * ES + SKT * KSS + SKT * VSS + BQ * KSS
                           + 16 * OSS + 512 + 16) * sizeof(float);

    static bool configured = false;
    if (!configured) {
        cudaFuncSetAttribute(attn_tf32_kernel,
                             cudaFuncAttributeMaxDynamicSharedMemorySize,
                             (int)smem);
        configured = true;
    }

    dim3 grid(LQ / BQ, BATCH * HEADS);   // (128, 64)
    attn_tf32_kernel<<<grid, NTHREADS, smem>>>(q, k, v, out);
}

// round 4
// speedup vs baseline: 1.1336x; 1.0186x over previous
#include <cuda_runtime.h>
#include <cstdint>
#include <cstddef>

// Problem constants
#define BATCH 4
#define HEADS 16
#define LQ 2048
#define SK 2048
#define DH 64

// Tiling
#define BQ   16      // query rows per CTA
#define SKT  128     // s-tile
#define ES   2052    // padded stride of E tile (floats)
#define KSS  68      // padded stride of K/Q tiles (floats) -> conflict-free QK B-frag loads
#define VSS  72      // padded stride of V tile -> conflict-free transposed B-frag loads
#define OSS  65      // padded stride of O scratch

#define NTHREADS 512
#define NWARPS   16

__device__ __forceinline__ uint32_t f2tf32(float f) {
    uint32_t u;
    asm("cvt.rna.tf32.f32 %0, %1;" : "=r"(u) : "f"(f));
    return u;
}

__device__ __forceinline__ void mma_tf32(float c[4], const uint32_t a[4], const uint32_t b[2]) {
    asm volatile(
        "mma.sync.aligned.m16n8k8.row.col.f32.tf32.tf32.f32 "
        "{%0,%1,%2,%3}, {%4,%5,%6,%7}, {%8,%9}, {%0,%1,%2,%3};"
        : "+f"(c[0]), "+f"(c[1]), "+f"(c[2]), "+f"(c[3])
        : "r"(a[0]), "r"(a[1]), "r"(a[2]), "r"(a[3]),
          "r"(b[0]), "r"(b[1]));
}

// ---- packed f32x2 helpers (FMA-pipe exp path) ----
__device__ __forceinline__ unsigned long long pk2(float a, float b) {
    unsigned long long r;
    asm("mov.b64 %0, {%1,%2};" : "=l"(r) : "f"(a), "f"(b));
    return r;
}
__device__ __forceinline__ void upk2(unsigned long long p, float& a, float& b) {
    asm("mov.b64 {%0,%1}, %2;" : "=f"(a), "=f"(b) : "l"(p));
}
__device__ __forceinline__ unsigned long long fma2(unsigned long long a,
                                                   unsigned long long b,
                                                   unsigned long long c) {
    unsigned long long d;
    asm("fma.rn.f32x2 %0, %1, %2, %3;" : "=l"(d) : "l"(a), "l"(b), "l"(c));
    return d;
}
__device__ __forceinline__ float ex2(float x) {
    float y;
    asm("ex2.approx.f32 %0, %1;" : "=f"(y) : "f"(x));
    return y;
}

// exp(x*0.125) for a pair, entirely on fma+alu pipes.
// K = 0.125*log2(e). n = round(x*K) via the 2^23+2^22 trick; r = x*K - n in [-0.5,0.5];
// 2^r via deg-4 Taylor Horner (max rel err ~4e-5); scale by 2^n via integer exponent add.
__device__ __forceinline__ void exp8_pair(float x0, float x1, float& e0, float& e1) {
    const float KKf  = 0.18033688011112042f;   // 0.125 * log2(e)
    const float RNDf = 12582912.0f;            // 2^23 + 2^22
    unsigned long long K2   = pk2(KKf, KKf);
    unsigned long long RND2 = pk2(RNDf, RNDf);
    unsigned long long N1   = pk2(-1.0f, -1.0f);
    unsigned long long C4   = pk2(0.009618127f, 0.009618127f);  // ln2^4/24
    unsigned long long C3   = pk2(0.055504109f, 0.055504109f);  // ln2^3/6
    unsigned long long C2   = pk2(0.240226507f, 0.240226507f);  // ln2^2/2
    unsigned long long C1   = pk2(0.693147181f, 0.693147181f);  // ln2
    unsigned long long ONE  = pk2(1.0f, 1.0f);

    unsigned long long X = pk2(x0, x1);
    unsigned long long T = fma2(X, K2, RND2);   // t = x*K + RND  (n in low mantissa bits)
    unsigned long long W = fma2(T, N1, RND2);   // w = RND - t = -n
    unsigned long long R = fma2(X, K2, W);      // r = x*K - n
    unsigned long long P = fma2(R, C4, C3);
    P = fma2(P, R, C2);
    P = fma2(P, R, C1);
    P = fma2(P, R, ONE);

    float t0, t1, p0, p1;
    upk2(T, t0, t1);
    upk2(P, p0, p1);
    // bits(t)<<23 == n<<23 exactly (low 9 bits of bits(12582912.f) are zero)
    e0 = __int_as_float(__float_as_int(p0) + (__float_as_int(t0) << 23));
    e1 = __int_as_float(__float_as_int(p1) + (__float_as_int(t1) << 23));
}

__global__ __launch_bounds__(NTHREADS, 1)
void attn_tf32_kernel(const float* __restrict__ q,
                      const float* __restrict__ k,
                      const float* __restrict__ v,
                      float* __restrict__ out) {
    extern __shared__ float sm[];
    float* Es  = sm;                       // [BQ][ES]   unnormalized exp(logits)
    float* Ks  = Es  + BQ * ES;            // [SKT][KSS]
    float* Vs  = Ks  + SKT * KSS;          // [SKT][VSS]
    float* Qs  = Vs  + SKT * VSS;          // [BQ][KSS]
    float* Os  = Qs  + BQ * KSS;           // [16][OSS]  O accumulation scratch
    float* red = Os  + 16 * OSS;           // [16][32]   partial row sums
    float* inv = red + 512;                // [16]

    const int bh  = blockIdx.y;
    const int q0  = blockIdx.x * BQ;

    const float* qp = q + ((size_t)bh * LQ + q0) * DH;
    const float* kp = k + (size_t)bh * SK * DH;
    const float* vp = v + (size_t)bh * SK * DH;
    float* op = out + ((size_t)bh * LQ + q0) * DH;
    float* sp = out + (size_t)BATCH * HEADS * LQ * DH
                    + ((size_t)bh * LQ + q0) * (size_t)SK;

    const int tid  = threadIdx.x;
    const int lane = tid & 31;
    const int warp = tid >> 5;
    const int gr   = lane >> 2;   // group row (0..7)
    const int tg   = lane & 3;    // thread-in-group (0..3)

    // ---- zero O scratch (ALL 16*OSS floats) ----
    for (int i = tid; i < 16 * OSS; i += NTHREADS) Os[i] = 0.f;

    // ---- load Q tile (16 x 64) ----
    if (tid < 256) {
        int r = tid >> 4, c4 = tid & 15;
        *(float4*)(Qs + r * KSS + c4 * 4) =
            *(const float4*)(qp + (size_t)r * DH + c4 * 4);
    }
    __syncthreads();

    // ---- Q A-fragments (tf32), identical in every warp, register-resident ----
    uint32_t qa[8][4];
#pragma unroll
    for (int ks = 0; ks < 8; ks++) {
        qa[ks][0] = f2tf32(Qs[gr * KSS + ks * 8 + tg]);
        qa[ks][1] = f2tf32(Qs[(gr + 8) * KSS + ks * 8 + tg]);
        qa[ks][2] = f2tf32(Qs[gr * KSS + ks * 8 + tg + 4]);
        qa[ks][3] = f2tf32(Qs[(gr + 8) * KSS + ks * 8 + tg + 4]);
    }

    // per-warp O partial accumulators: 16 rows x 64 cols (8 n-chunks of m16n8)
    float o[8][4];
#pragma unroll
    for (int j = 0; j < 8; j++) { o[j][0] = o[j][1] = o[j][2] = o[j][3] = 0.f; }

    const int n0 = warp * 8;   // this warp's 8 s-columns within the tile

    // ==================== Fused pass: E = exp(QK^T*scale); O += E@V ====================
    for (int s0 = 0; s0 < SK; s0 += SKT) {
        __syncthreads();  // protect Ks/Vs from previous iteration readers
        // load K tile 128x64 and V tile 128x64 (4 float4 each per thread), coalesced
#pragma unroll
        for (int i = 0; i < 4; i++) {
            int idx = tid + i * NTHREADS;
            int r = idx >> 4, c4 = idx & 15;
            *(float4*)(Ks + r * KSS + c4 * 4) =
                *(const float4*)(kp + (size_t)(s0 + r) * DH + c4 * 4);
        }
#pragma unroll
        for (int i = 0; i < 4; i++) {
            int idx = tid + i * NTHREADS;
            int r = idx >> 4, c4 = idx & 15;
            *(float4*)(Vs + r * VSS + c4 * 4) =
                *(const float4*)(vp + (size_t)(s0 + r) * DH + c4 * 4);
        }
        __syncthreads();

        // --- QK^T for this warp's 8 columns ---
        float acc[4] = {0.f, 0.f, 0.f, 0.f};
#pragma unroll
        for (int ks = 0; ks < 8; ks++) {
            uint32_t b[2];
            b[0] = f2tf32(Ks[(n0 + gr) * KSS + ks * 8 + tg]);
            b[1] = f2tf32(Ks[(n0 + gr) * KSS + ks * 8 + tg + 4]);
            mma_tf32(acc, qa[ks], b);
        }

        // --- exp(acc * 0.125): alternate pipes per s-tile (hybrid MUFU / FMA-poly) ---
        float e0, e1, e2, e3;
        if ((s0 & SKT) == 0) {
            // FMA+ALU pipe polynomial path
            exp8_pair(acc[0], acc[1], e0, e1);
            exp8_pair(acc[2], acc[3], e2, e3);
        } else {
            // MUFU path
            const float KKf = 0.18033688011112042f;  // 0.125*log2(e)
            e0 = ex2(acc[0] * KKf);
            e1 = ex2(acc[1] * KKf);
            e2 = ex2(acc[2] * KKf);
            e3 = ex2(acc[3] * KKf);
        }
        {
            int colb = s0 + n0 + 2 * tg;
            *(float2*)(Es + gr * ES + colb)       = make_float2(e0, e1);
            *(float2*)(Es + (gr + 8) * ES + colb) = make_float2(e2, e3);
        }
        __syncwarp();

        // --- read back own columns as A fragment (k=8 chunk) ---
        uint32_t a[4];
        a[0] = f2tf32(Es[gr * ES + s0 + n0 + tg]);
        a[1] = f2tf32(Es[(gr + 8) * ES + s0 + n0 + tg]);
        a[2] = f2tf32(Es[gr * ES + s0 + n0 + tg + 4]);
        a[3] = f2tf32(Es[(gr + 8) * ES + s0 + n0 + tg + 4]);

        // --- O += E_chunk @ V_chunk  (m16 k8 n64, warp's 8 V rows) ---
        const int vr = warp * 8;
#pragma unroll
        for (int j = 0; j < 8; j++) {
            uint32_t b[2];
            b[0] = f2tf32(Vs[(vr + tg) * VSS + j * 8 + gr]);
            b[1] = f2tf32(Vs[(vr + tg + 4) * VSS + j * 8 + gr]);
            mma_tf32(o[j], a, b);
        }
    }

    // ==================== Reduce O partials across warps (SMEM atomics) ====================
#pragma unroll
    for (int j = 0; j < 8; j++) {
        int c = j * 8 + 2 * tg;
        atomicAdd(&Os[gr * OSS + c],           o[j][0]);
        atomicAdd(&Os[gr * OSS + c + 1],       o[j][1]);
        atomicAdd(&Os[(gr + 8) * OSS + c],     o[j][2]);
        atomicAdd(&Os[(gr + 8) * OSS + c + 1], o[j][3]);
    }
    __syncthreads();

    // ==================== Row sums -> 1/sum ====================
    {
        int r = tid >> 5, c = tid & 31;
        float s = 0.f;
#pragma unroll 8
        for (int j = 0; j < SK / 32; j++)
            s += Es[r * ES + c + j * 32];
        red[r * 32 + c] = s;
    }
    __syncthreads();
    if (tid < 16) {
        float s = 0.f;
#pragma unroll
        for (int j = 0; j < 32; j++) s += red[tid * 32 + j];
        inv[tid] = 1.0f / s;
    }
    __syncthreads();

    // ==================== Write normalized scores ====================
    {
        // 16*2048 floats = 8192 float4, 16 per thread; coalesced float4 stores
#pragma unroll
        for (int i = 0; i < 16; i++) {
            int idx = tid + i * NTHREADS;     // float4 index
            int r  = idx >> 9;                // 512 float4 per row
            int c4 = idx & 511;
            float4 e = *(float4*)(Es + r * ES + c4 * 4);
            float is = inv[r];
            e.x *= is; e.y *= is; e.z *= is; e.w *= is;
            *(float4*)(sp + (size_t)r * SK + c4 * 4) = e;
        }
    }

    // ==================== Write O ====================
    {
#pragma unroll
        for (int i = 0; i < 2; i++) {
            int idx = tid + i * NTHREADS;     // 0..1023
            int r = idx >> 6, c = idx & 63;
            op[(size_t)r * DH + c] = Os[r * OSS + c] * inv[r];
        }
    }
}

extern "C" void kernel_launch(void* const* d_in, const int* in_sizes, int n_in,
                              void* d_out, int out_size) {
    const float* q = (const float*)d_in[0];
    const float* k = (const float*)d_in[1];
    const float* v = (const float*)d_in[2];
    float* out = (float*)d_out;

    // dynamic SMEM (floats): E + K + V + Q + Os + red + inv
    size_t smem = (size_t)(BQ * ES + SKT * KSS + SKT * VSS + BQ * KSS
                           + 16 * OSS + 512 + 16) * sizeof(float);

    static bool configured = false;
    if (!configured) {
        cudaFuncSetAttribute(attn_tf32_kernel,
                             cudaFuncAttributeMaxDynamicSharedMemorySize,
                             (int)smem);
        configured = true;
    }

    dim3 grid(LQ / BQ, BATCH * HEADS);   // (128, 64)
    attn_tf32_kernel<<<grid, NTHREADS, smem>>>(q, k, v, out);
}

// round 5
// speedup vs baseline: 1.4962x; 1.3199x over previous
#include <cuda_runtime.h>
#include <cstdint>
#include <cstddef>

// Problem constants
#define BATCH 4
#define HEADS 16
#define LQ 2048
#define SK 2048
#define DH 64

// Tiling
#define BQ   16      // query rows per CTA
#define SKT  128     // s-columns per iteration; each warp owns 16
#define KPS  68      // padded stride K private tile / Q tile
#define VPS  72      // padded stride V private tile
#define OSS  65      // padded stride O scratch

#define NTHREADS 256
#define NWARPS   8

__device__ __forceinline__ uint32_t f2tf32(float f) {
    uint32_t u;
    asm("cvt.rna.tf32.f32 %0, %1;" : "=r"(u) : "f"(f));
    return u;
}

__device__ __forceinline__ void mma_tf32(float c[4], const uint32_t a[4], const uint32_t b[2]) {
    asm volatile(
        "mma.sync.aligned.m16n8k8.row.col.f32.tf32.tf32.f32 "
        "{%0,%1,%2,%3}, {%4,%5,%6,%7}, {%8,%9}, {%0,%1,%2,%3};"
        : "+f"(c[0]), "+f"(c[1]), "+f"(c[2]), "+f"(c[3])
        : "r"(a[0]), "r"(a[1]), "r"(a[2]), "r"(a[3]),
          "r"(b[0]), "r"(b[1]));
}

// ---- packed f32x2 helpers (FMA-pipe exp path) ----
__device__ __forceinline__ unsigned long long pk2(float a, float b) {
    unsigned long long r;
    asm("mov.b64 %0, {%1,%2};" : "=l"(r) : "f"(a), "f"(b));
    return r;
}
__device__ __forceinline__ void upk2(unsigned long long p, float& a, float& b) {
    asm("mov.b64 {%0,%1}, %2;" : "=f"(a), "=f"(b) : "l"(p));
}
__device__ __forceinline__ unsigned long long fma2(unsigned long long a,
                                                   unsigned long long b,
                                                   unsigned long long c) {
    unsigned long long d;
    asm("fma.rn.f32x2 %0, %1, %2, %3;" : "=l"(d) : "l"(a), "l"(b), "l"(c));
    return d;
}
__device__ __forceinline__ float ex2(float x) {
    float y;
    asm("ex2.approx.f32 %0, %1;" : "=f"(y) : "f"(x));
    return y;
}

// exp(x*0.125) for a pair, entirely on fma+alu pipes (deg-4, rel err ~4e-5).
__device__ __forceinline__ void exp8_pair(float x0, float x1, float& e0, float& e1) {
    const float KKf  = 0.18033688011112042f;   // 0.125 * log2(e)
    const float RNDf = 12582912.0f;            // 2^23 + 2^22
    unsigned long long K2   = pk2(KKf, KKf);
    unsigned long long RND2 = pk2(RNDf, RNDf);
    unsigned long long N1   = pk2(-1.0f, -1.0f);
    unsigned long long C4   = pk2(0.009618127f, 0.009618127f);
    unsigned long long C3   = pk2(0.055504109f, 0.055504109f);
    unsigned long long C2   = pk2(0.240226507f, 0.240226507f);
    unsigned long long C1   = pk2(0.693147181f, 0.693147181f);
    unsigned long long ONE  = pk2(1.0f, 1.0f);

    unsigned long long X = pk2(x0, x1);
    unsigned long long T = fma2(X, K2, RND2);   // n in low mantissa bits
    unsigned long long W = fma2(T, N1, RND2);   // -n
    unsigned long long R = fma2(X, K2, W);      // r = x*K - n
    unsigned long long P = fma2(R, C4, C3);
    P = fma2(P, R, C2);
    P = fma2(P, R, C1);
    P = fma2(P, R, ONE);

    float t0, t1, p0, p1;
    upk2(T, t0, t1);
    upk2(P, p0, p1);
    e0 = __int_as_float(__float_as_int(p0) + (__float_as_int(t0) << 23));
    e1 = __int_as_float(__float_as_int(p1) + (__float_as_int(t1) << 23));
}

__global__ __launch_bounds__(NTHREADS, 2)
void attn_tf32_kernel(const float* __restrict__ q,
                      const float* __restrict__ k,
                      const float* __restrict__ v,
                      float* __restrict__ out) {
    extern __shared__ float sm[];
    // Warp-private K/V staging => NO __syncthreads in main loop.
    // layout: K[8][16*KPS], V[8][16*VPS], Q[16*KPS], Os[16*OSS], red[16], inv[16]
    const int tid  = threadIdx.x;
    const int lane = tid & 31;
    const int warp = tid >> 5;
    const int gr   = lane >> 2;   // 0..7
    const int tg   = lane & 3;    // 0..3

    float* Kw  = sm + warp * (16 * KPS);
    float* Vw  = sm + NWARPS * 16 * KPS + warp * (16 * VPS);
    float* Qs  = sm + NWARPS * 16 * (KPS + VPS);
    float* Os  = Qs + 16 * KPS;
    float* red = Os + 16 * OSS;
    float* inv = red + 16;

    const int bh  = blockIdx.y;
    const int q0  = blockIdx.x * BQ;

    const float* qp = q + ((size_t)bh * LQ + q0) * DH;
    const float* kp = k + (size_t)bh * SK * DH;
    const float* vp = v + (size_t)bh * SK * DH;
    float* op = out + ((size_t)bh * LQ + q0) * DH;
    float* sp = out + (size_t)BATCH * HEADS * LQ * DH
                    + ((size_t)bh * LQ + q0) * (size_t)SK;

    // ---- zero scratch ----
    for (int i = tid; i < 16 * OSS; i += NTHREADS) Os[i] = 0.f;
    if (tid < 16) red[tid] = 0.f;

    // ---- load Q tile (16 x 64) : one float4 per thread ----
    {
        int r = tid >> 4, c4 = tid & 15;
        *(float4*)(Qs + r * KPS + c4 * 4) =
            *(const float4*)(qp + (size_t)r * DH + c4 * 4);
    }
    __syncthreads();

    // ---- Q A-fragments (tf32), register-resident ----
    uint32_t qa[8][4];
#pragma unroll
    for (int ks = 0; ks < 8; ks++) {
        qa[ks][0] = f2tf32(Qs[gr * KPS + ks * 8 + tg]);
        qa[ks][1] = f2tf32(Qs[(gr + 8) * KPS + ks * 8 + tg]);
        qa[ks][2] = f2tf32(Qs[gr * KPS + ks * 8 + tg + 4]);
        qa[ks][3] = f2tf32(Qs[(gr + 8) * KPS + ks * 8 + tg + 4]);
    }

    // per-warp O accumulators: 16 rows x 64 cols (8 n-chunks of m16n8)
    float o[8][4];
#pragma unroll
    for (int j = 0; j < 8; j++) { o[j][0] = o[j][1] = o[j][2] = o[j][3] = 0.f; }

    float rs0 = 0.f, rs1 = 0.f;            // row-sum partials (rows gr, gr+8)
    const int wc = warp * 16;              // warp's 16 columns within tile
    const float KKf = 0.18033688011112042f;

    // shuffle source lanes for C-frag -> A-frag redistribution
    const int s1 = (lane & 28) | (tg >> 1);
    const int s2 = s1 + 2;
    const bool odd = (tg & 1);

    // ==================== barrier-free main loop ====================
    for (int s0 = 0; s0 < SK; s0 += SKT) {
        const float* kpt = kp + (size_t)(s0 + wc) * DH;
        const float* vpt = vp + (size_t)(s0 + wc) * DH;
        __syncwarp();   // WAR: previous iter's LDS done before overwrite
#pragma unroll
        for (int i = 0; i < 8; i++) {
            int idx = lane + i * 32;
            int r = idx >> 4, c4 = idx & 15;
            *(float4*)(Kw + r * KPS + c4 * 4) =
                *(const float4*)(kpt + (size_t)r * DH + c4 * 4);
        }
#pragma unroll
        for (int i = 0; i < 8; i++) {
            int idx = lane + i * 32;
            int r = idx >> 4, c4 = idx & 15;
            *(float4*)(Vw + r * VPS + c4 * 4) =
                *(const float4*)(vpt + (size_t)r * DH + c4 * 4);
        }
        __syncwarp();

        // --- QK^T: two independent 8-col chunks ---
        float acc0[4] = {0.f, 0.f, 0.f, 0.f};
        float acc1[4] = {0.f, 0.f, 0.f, 0.f};
#pragma unroll
        for (int ks = 0; ks < 8; ks++) {
            uint32_t b0[2], b1[2];
            b0[0] = f2tf32(Kw[gr * KPS + ks * 8 + tg]);
            b0[1] = f2tf32(Kw[gr * KPS + ks * 8 + tg + 4]);
            b1[0] = f2tf32(Kw[(8 + gr) * KPS + ks * 8 + tg]);
            b1[1] = f2tf32(Kw[(8 + gr) * KPS + ks * 8 + tg + 4]);
            mma_tf32(acc0, qa[ks], b0);
            mma_tf32(acc1, qa[ks], b1);
        }

        // --- exp: chunk0 on fma-poly, chunk1 on MUFU (pipe balance) ---
        float e0, e1, e2, e3;
        exp8_pair(acc0[0], acc0[1], e0, e1);
        exp8_pair(acc0[2], acc0[3], e2, e3);
        float f0 = ex2(acc1[0] * KKf);
        float f1 = ex2(acc1[1] * KKf);
        float f2 = ex2(acc1[2] * KKf);
        float f3 = ex2(acc1[3] * KKf);

        rs0 += (e0 + e1) + (f0 + f1);
        rs1 += (e2 + e3) + (f2 + f3);

        // --- write unnormalized scores straight to GMEM ---
        {
            int gcol = s0 + wc + 2 * tg;
            *(float2*)(sp + (size_t)gr * SK + gcol)           = make_float2(e0, e1);
            *(float2*)(sp + (size_t)(gr + 8) * SK + gcol)     = make_float2(e2, e3);
            *(float2*)(sp + (size_t)gr * SK + gcol + 8)       = make_float2(f0, f1);
            *(float2*)(sp + (size_t)(gr + 8) * SK + gcol + 8) = make_float2(f2, f3);
        }

        // --- C-frag -> A-frag via quad shuffles (no SMEM round trip) ---
        uint32_t a0[4], a1[4];
        {
            float u, w;
            u = __shfl_sync(0xffffffffu, e0, s1);
            w = __shfl_sync(0xffffffffu, e1, s1);
            a0[0] = f2tf32(odd ? w : u);
            u = __shfl_sync(0xffffffffu, e2, s1);
            w = __shfl_sync(0xffffffffu, e3, s1);
            a0[1] = f2tf32(odd ? w : u);
            u = __shfl_sync(0xffffffffu, e0, s2);
            w = __shfl_sync(0xffffffffu, e1, s2);
            a0[2] = f2tf32(odd ? w : u);
            u = __shfl_sync(0xffffffffu, e2, s2);
            w = __shfl_sync(0xffffffffu, e3, s2);
            a0[3] = f2tf32(odd ? w : u);

            u = __shfl_sync(0xffffffffu, f0, s1);
            w = __shfl_sync(0xffffffffu, f1, s1);
            a1[0] = f2tf32(odd ? w : u);
            u = __shfl_sync(0xffffffffu, f2, s1);
            w = __shfl_sync(0xffffffffu, f3, s1);
            a1[1] = f2tf32(odd ? w : u);
            u = __shfl_sync(0xffffffffu, f0, s2);
            w = __shfl_sync(0xffffffffu, f1, s2);
            a1[2] = f2tf32(odd ? w : u);
            u = __shfl_sync(0xffffffffu, f2, s2);
            w = __shfl_sync(0xffffffffu, f3, s2);
            a1[3] = f2tf32(odd ? w : u);
        }

        // --- PV: chunk0 uses V rows 0..7 (warp-local), chunk1 rows 8..15 ---
#pragma unroll
        for (int j = 0; j < 8; j++) {
            uint32_t b[2];
            b[0] = f2tf32(Vw[tg * VPS + j * 8 + gr]);
            b[1] = f2tf32(Vw[(tg + 4) * VPS + j * 8 + gr]);
            mma_tf32(o[j], a0, b);
        }
#pragma unroll
        for (int j = 0; j < 8; j++) {
            uint32_t b[2];
            b[0] = f2tf32(Vw[(8 + tg) * VPS + j * 8 + gr]);
            b[1] = f2tf32(Vw[(8 + tg + 4) * VPS + j * 8 + gr]);
            mma_tf32(o[j], a1, b);
        }
    }

    // ==================== reductions ====================
    // row sums: quad reduce, then one atomic per row per warp
    rs0 += __shfl_xor_sync(0xffffffffu, rs0, 1);
    rs0 += __shfl_xor_sync(0xffffffffu, rs0, 2);
    rs1 += __shfl_xor_sync(0xffffffffu, rs1, 1);
    rs1 += __shfl_xor_sync(0xffffffffu, rs1, 2);
    if (tg == 0) {
        atomicAdd(&red[gr], rs0);
        atomicAdd(&red[gr + 8], rs1);
    }
    // O partials
#pragma unroll
    for (int j = 0; j < 8; j++) {
        int c = j * 8 + 2 * tg;
        atomicAdd(&Os[gr * OSS + c],           o[j][0]);
        atomicAdd(&Os[gr * OSS + c + 1],       o[j][1]);
        atomicAdd(&Os[(gr + 8) * OSS + c],     o[j][2]);
        atomicAdd(&Os[(gr + 8) * OSS + c + 1], o[j][3]);
    }
    __syncthreads();
    if (tid < 16) inv[tid] = 1.0f / red[tid];
    __syncthreads();

    // ==================== normalize scores in-place (L2-resident) ====================
    {
#pragma unroll
        for (int i = 0; i < 32; i++) {
            int idx = tid + i * NTHREADS;     // float4 index within 16x2048
            int r  = idx >> 9;                // 512 float4 per row
            int c4 = idx & 511;
            float4 e = *(float4*)(sp + (size_t)r * SK + c4 * 4);
            float is = inv[r];
            e.x *= is; e.y *= is; e.z *= is; e.w *= is;
            *(float4*)(sp + (size_t)r * SK + c4 * 4) = e;
        }
    }

    // ==================== write O ====================
    {
#pragma unroll
        for (int i = 0; i < 4; i++) {
            int idx = tid + i * NTHREADS;     // 0..1023
            int r = idx >> 6, c = idx & 63;
            op[(size_t)r * DH + c] = Os[r * OSS + c] * inv[r];
        }
    }
}

extern "C" void kernel_launch(void* const* d_in, const int* in_sizes, int n_in,
                              void* d_out, int out_size) {
    const float* q = (const float*)d_in[0];
    const float* k = (const float*)d_in[1];
    const float* v = (const float*)d_in[2];
    float* out = (float*)d_out;

    // SMEM (floats): 8*16*KPS + 8*16*VPS + 16*KPS + 16*OSS + 16 + 16
    size_t smem = (size_t)(NWARPS * 16 * KPS + NWARPS * 16 * VPS
                           + 16 * KPS + 16 * OSS + 32) * sizeof(float);

    static bool configured = false;
    if (!configured) {
        cudaFuncSetAttribute(attn_tf32_kernel,
                             cudaFuncAttributeMaxDynamicSharedMemorySize,
                             (int)smem);
        configured = true;
    }

    dim3 grid(LQ / BQ, BATCH * HEADS);   // (128, 64)
    attn_tf32_kernel<<<grid, NTHREADS, smem>>>(q, k, v, out);
}

// round 6
// speedup vs baseline: 1.4971x; 1.0006x over previous
#include <cuda_runtime.h>
#include <cstdint>
#include <cstddef>

// Problem constants
#define BATCH 4
#define HEADS 16
#define LQ 2048
#define SK 2048
#define DH 64

// Tiling
#define BQ   16      // query rows per CTA
#define SKT  128     // s-columns per iteration; each warp owns 16
#define KPS  68      // padded stride K private tile / Q tile
#define VPS  72      // padded stride V private tile
#define OSS  65      // padded stride O scratch

#define NTHREADS 256
#define NWARPS   8

__device__ __forceinline__ uint32_t f2tf32(float f) {
    uint32_t u;
    asm("cvt.rna.tf32.f32 %0, %1;" : "=r"(u) : "f"(f));
    return u;
}

__device__ __forceinline__ void mma_tf32(float c[4], const uint32_t a[4], const uint32_t b[2]) {
    asm volatile(
        "mma.sync.aligned.m16n8k8.row.col.f32.tf32.tf32.f32 "
        "{%0,%1,%2,%3}, {%4,%5,%6,%7}, {%8,%9}, {%0,%1,%2,%3};"
        : "+f"(c[0]), "+f"(c[1]), "+f"(c[2]), "+f"(c[3])
        : "r"(a[0]), "r"(a[1]), "r"(a[2]), "r"(a[3]),
          "r"(b[0]), "r"(b[1]));
}

// ---- packed f32x2 helpers (FMA-pipe exp path) ----
__device__ __forceinline__ unsigned long long pk2(float a, float b) {
    unsigned long long r;
    asm("mov.b64 %0, {%1,%2};" : "=l"(r) : "f"(a), "f"(b));
    return r;
}
__device__ __forceinline__ void upk2(unsigned long long p, float& a, float& b) {
    asm("mov.b64 {%0,%1}, %2;" : "=f"(a), "=f"(b) : "l"(p));
}
__device__ __forceinline__ unsigned long long fma2(unsigned long long a,
                                                   unsigned long long b,
                                                   unsigned long long c) {
    unsigned long long d;
    asm("fma.rn.f32x2 %0, %1, %2, %3;" : "=l"(d) : "l"(a), "l"(b), "l"(c));
    return d;
}
__device__ __forceinline__ float ex2(float x) {
    float y;
    asm("ex2.approx.f32 %0, %1;" : "=f"(y) : "f"(x));
    return y;
}

// exp(x*0.125) for a pair, entirely on fma+alu pipes (deg-4, rel err ~4e-5).
__device__ __forceinline__ void exp8_pair(float x0, float x1, float& e0, float& e1) {
    const float KKf  = 0.18033688011112042f;   // 0.125 * log2(e)
    const float RNDf = 12582912.0f;            // 2^23 + 2^22
    unsigned long long K2   = pk2(KKf, KKf);
    unsigned long long RND2 = pk2(RNDf, RNDf);
    unsigned long long N1   = pk2(-1.0f, -1.0f);
    unsigned long long C4   = pk2(0.009618127f, 0.009618127f);
    unsigned long long C3   = pk2(0.055504109f, 0.055504109f);
    unsigned long long C2   = pk2(0.240226507f, 0.240226507f);
    unsigned long long C1   = pk2(0.693147181f, 0.693147181f);
    unsigned long long ONE  = pk2(1.0f, 1.0f);

    unsigned long long X = pk2(x0, x1);
    unsigned long long T = fma2(X, K2, RND2);   // n in low mantissa bits
    unsigned long long W = fma2(T, N1, RND2);   // -n
    unsigned long long R = fma2(X, K2, W);      // r = x*K - n
    unsigned long long P = fma2(R, C4, C3);
    P = fma2(P, R, C2);
    P = fma2(P, R, C1);
    P = fma2(P, R, ONE);

    float t0, t1, p0, p1;
    upk2(T, t0, t1);
    upk2(P, p0, p1);
    e0 = __int_as_float(__float_as_int(p0) + (__float_as_int(t0) << 23));
    e1 = __int_as_float(__float_as_int(p1) + (__float_as_int(t1) << 23));
}

__global__ __launch_bounds__(NTHREADS, 2)
void attn_tf32_kernel(const float* __restrict__ q,
                      const float* __restrict__ k,
                      const float* __restrict__ v,
                      float* __restrict__ out) {
    extern __shared__ float sm[];
    // Warp-private K/V staging => NO __syncthreads in main loop.
    // layout: K[8][16*KPS], V[8][16*VPS], Q[16*KPS], Os[16*OSS], red[16], inv[16]
    const int tid  = threadIdx.x;
    const int lane = tid & 31;
    const int warp = tid >> 5;
    const int gr   = lane >> 2;   // 0..7
    const int tg   = lane & 3;    // 0..3

    float* Kw  = sm + warp * (16 * KPS);
    float* Vw  = sm + NWARPS * 16 * KPS + warp * (16 * VPS);
    float* Qs  = sm + NWARPS * 16 * (KPS + VPS);
    float* Os  = Qs + 16 * KPS;
    float* red = Os + 16 * OSS;
    float* inv = red + 16;

    const int bh  = blockIdx.y;
    const int q0  = blockIdx.x * BQ;

    const float* qp = q + ((size_t)bh * LQ + q0) * DH;
    const float* kp = k + (size_t)bh * SK * DH;
    const float* vp = v + (size_t)bh * SK * DH;
    float* op = out + ((size_t)bh * LQ + q0) * DH;
    float* sp = out + (size_t)BATCH * HEADS * LQ * DH
                    + ((size_t)bh * LQ + q0) * (size_t)SK;

    // ---- zero scratch ----
    for (int i = tid; i < 16 * OSS; i += NTHREADS) Os[i] = 0.f;
    if (tid < 16) red[tid] = 0.f;

    // ---- load Q tile (16 x 64) : one float4 per thread ----
    {
        int r = tid >> 4, c4 = tid & 15;
        *(float4*)(Qs + r * KPS + c4 * 4) =
            *(const float4*)(qp + (size_t)r * DH + c4 * 4);
    }
    __syncthreads();

    // ---- Q A-fragments (tf32), register-resident ----
    uint32_t qa[8][4];
#pragma unroll
    for (int ks = 0; ks < 8; ks++) {
        qa[ks][0] = f2tf32(Qs[gr * KPS + ks * 8 + tg]);
        qa[ks][1] = f2tf32(Qs[(gr + 8) * KPS + ks * 8 + tg]);
        qa[ks][2] = f2tf32(Qs[gr * KPS + ks * 8 + tg + 4]);
        qa[ks][3] = f2tf32(Qs[(gr + 8) * KPS + ks * 8 + tg + 4]);
    }

    // per-warp O accumulators: 16 rows x 64 cols (8 n-chunks of m16n8)
    float o[8][4];
#pragma unroll
    for (int j = 0; j < 8; j++) { o[j][0] = o[j][1] = o[j][2] = o[j][3] = 0.f; }

    float rs0 = 0.f, rs1 = 0.f;            // row-sum partials (rows gr, gr+8)
    const int wc = warp * 16;              // warp's 16 columns within tile
    const float KKf = 0.18033688011112042f;

    // shuffle source lanes for C-frag -> A-frag redistribution
    const int s1 = (lane & 28) | (tg >> 1);
    const int s2 = s1 + 2;
    const bool odd = (tg & 1);

    // ==================== barrier-free main loop ====================
    for (int s0 = 0; s0 < SK; s0 += SKT) {
        const float* kpt = kp + (size_t)(s0 + wc) * DH;
        const float* vpt = vp + (size_t)(s0 + wc) * DH;
        __syncwarp();   // WAR: previous iter's LDS done before overwrite
#pragma unroll
        for (int i = 0; i < 8; i++) {
            int idx = lane + i * 32;
            int r = idx >> 4, c4 = idx & 15;
            *(float4*)(Kw + r * KPS + c4 * 4) =
                *(const float4*)(kpt + (size_t)r * DH + c4 * 4);
        }
#pragma unroll
        for (int i = 0; i < 8; i++) {
            int idx = lane + i * 32;
            int r = idx >> 4, c4 = idx & 15;
            *(float4*)(Vw + r * VPS + c4 * 4) =
                *(const float4*)(vpt + (size_t)r * DH + c4 * 4);
        }
        __syncwarp();

        // --- QK^T: two independent 8-col chunks ---
        float acc0[4] = {0.f, 0.f, 0.f, 0.f};
        float acc1[4] = {0.f, 0.f, 0.f, 0.f};
#pragma unroll
        for (int ks = 0; ks < 8; ks++) {
            uint32_t b0[2], b1[2];
            b0[0] = f2tf32(Kw[gr * KPS + ks * 8 + tg]);
            b0[1] = f2tf32(Kw[gr * KPS + ks * 8 + tg + 4]);
            b1[0] = f2tf32(Kw[(8 + gr) * KPS + ks * 8 + tg]);
            b1[1] = f2tf32(Kw[(8 + gr) * KPS + ks * 8 + tg + 4]);
            mma_tf32(acc0, qa[ks], b0);
            mma_tf32(acc1, qa[ks], b1);
        }

        // --- exp: chunk0 on fma-poly, chunk1 on MUFU (pipe balance) ---
        float e0, e1, e2, e3;
        exp8_pair(acc0[0], acc0[1], e0, e1);
        exp8_pair(acc0[2], acc0[3], e2, e3);
        float f0 = ex2(acc1[0] * KKf);
        float f1 = ex2(acc1[1] * KKf);
        float f2 = ex2(acc1[2] * KKf);
        float f3 = ex2(acc1[3] * KKf);

        rs0 += (e0 + e1) + (f0 + f1);
        rs1 += (e2 + e3) + (f2 + f3);

        // --- write unnormalized scores straight to GMEM ---
        {
            int gcol = s0 + wc + 2 * tg;
            *(float2*)(sp + (size_t)gr * SK + gcol)           = make_float2(e0, e1);
            *(float2*)(sp + (size_t)(gr + 8) * SK + gcol)     = make_float2(e2, e3);
            *(float2*)(sp + (size_t)gr * SK + gcol + 8)       = make_float2(f0, f1);
            *(float2*)(sp + (size_t)(gr + 8) * SK + gcol + 8) = make_float2(f2, f3);
        }

        // --- C-frag -> A-frag via quad shuffles (no SMEM round trip) ---
        uint32_t a0[4], a1[4];
        {
            float u, w;
            u = __shfl_sync(0xffffffffu, e0, s1);
            w = __shfl_sync(0xffffffffu, e1, s1);
            a0[0] = f2tf32(odd ? w : u);
            u = __shfl_sync(0xffffffffu, e2, s1);
            w = __shfl_sync(0xffffffffu, e3, s1);
            a0[1] = f2tf32(odd ? w : u);
            u = __shfl_sync(0xffffffffu, e0, s2);
            w = __shfl_sync(0xffffffffu, e1, s2);
            a0[2] = f2tf32(odd ? w : u);
            u = __shfl_sync(0xffffffffu, e2, s2);
            w = __shfl_sync(0xffffffffu, e3, s2);
            a0[3] = f2tf32(odd ? w : u);

            u = __shfl_sync(0xffffffffu, f0, s1);
            w = __shfl_sync(0xffffffffu, f1, s1);
            a1[0] = f2tf32(odd ? w : u);
            u = __shfl_sync(0xffffffffu, f2, s1);
            w = __shfl_sync(0xffffffffu, f3, s1);
            a1[1] = f2tf32(odd ? w : u);
            u = __shfl_sync(0xffffffffu, f0, s2);
            w = __shfl_sync(0xffffffffu, f1, s2);
            a1[2] = f2tf32(odd ? w : u);
            u = __shfl_sync(0xffffffffu, f2, s2);
            w = __shfl_sync(0xffffffffu, f3, s2);
            a1[3] = f2tf32(odd ? w : u);
        }

        // --- PV: chunk0 uses V rows 0..7 (warp-local), chunk1 rows 8..15 ---
#pragma unroll
        for (int j = 0; j < 8; j++) {
            uint32_t b[2];
            b[0] = f2tf32(Vw[tg * VPS + j * 8 + gr]);
            b[1] = f2tf32(Vw[(tg + 4) * VPS + j * 8 + gr]);
            mma_tf32(o[j], a0, b);
        }
#pragma unroll
        for (int j = 0; j < 8; j++) {
            uint32_t b[2];
            b[0] = f2tf32(Vw[(8 + tg) * VPS + j * 8 + gr]);
            b[1] = f2tf32(Vw[(8 + tg + 4) * VPS + j * 8 + gr]);
            mma_tf32(o[j], a1, b);
        }
    }

    // ==================== reductions ====================
    // row sums: quad reduce, then one atomic per row per warp
    rs0 += __shfl_xor_sync(0xffffffffu, rs0, 1);
    rs0 += __shfl_xor_sync(0xffffffffu, rs0, 2);
    rs1 += __shfl_xor_sync(0xffffffffu, rs1, 1);
    rs1 += __shfl_xor_sync(0xffffffffu, rs1, 2);
    if (tg == 0) {
        atomicAdd(&red[gr], rs0);
        atomicAdd(&red[gr + 8], rs1);
    }
    // O partials
#pragma unroll
    for (int j = 0; j < 8; j++) {
        int c = j * 8 + 2 * tg;
        atomicAdd(&Os[gr * OSS + c],           o[j][0]);
        atomicAdd(&Os[gr * OSS + c + 1],       o[j][1]);
        atomicAdd(&Os[(gr + 8) * OSS + c],     o[j][2]);
        atomicAdd(&Os[(gr + 8) * OSS + c + 1], o[j][3]);
    }
    __syncthreads();
    if (tid < 16) inv[tid] = 1.0f / red[tid];
    __syncthreads();

    // ==================== normalize scores in-place (L2-resident) ====================
    {
#pragma unroll
        for (int i = 0; i < 32; i++) {
            int idx = tid + i * NTHREADS;     // float4 index within 16x2048
            int r  = idx >> 9;                // 512 float4 per row
            int c4 = idx & 511;
            float4 e = *(float4*)(sp + (size_t)r * SK + c4 * 4);
            float is = inv[r];
            e.x *= is; e.y *= is; e.z *= is; e.w *= is;
            *(float4*)(sp + (size_t)r * SK + c4 * 4) = e;
        }
    }

    // ==================== write O ====================
    {
#pragma unroll
        for (int i = 0; i < 4; i++) {
            int idx = tid + i * NTHREADS;     // 0..1023
            int r = idx >> 6, c = idx & 63;
            op[(size_t)r * DH + c] = Os[r * OSS + c] * inv[r];
        }
    }
}

extern "C" void kernel_launch(void* const* d_in, const int* in_sizes, int n_in,
                              void* d_out, int out_size) {
    const float* q = (const float*)d_in[0];
    const float* k = (const float*)d_in[1];
    const float* v = (const float*)d_in[2];
    float* out = (float*)d_out;

    // SMEM (floats): 8*16*KPS + 8*16*VPS + 16*KPS + 16*OSS + 16 + 16
    size_t smem = (size_t)(NWARPS * 16 * KPS + NWARPS * 16 * VPS
                           + 16 * KPS + 16 * OSS + 32) * sizeof(float);

    static bool configured = false;
    if (!configured) {
        cudaFuncSetAttribute(attn_tf32_kernel,
                             cudaFuncAttributeMaxDynamicSharedMemorySize,
                             (int)smem);
        configured = true;
    }

    dim3 grid(LQ / BQ, BATCH * HEADS);   // (128, 64)
    attn_tf32_kernel<<<grid, NTHREADS, smem>>>(q, k, v, out);
}

// round 7
// speedup vs baseline: 2.1749x; 1.4527x over previous
#include <cuda_runtime.h>
#include <cstdint>
#include <cstddef>

// Problem constants
#define BATCH 4
#define HEADS 16
#define LQ 2048
#define SK 2048
#define DH 64

// Tiling
#define BQ   16      // query rows per CTA
#define SKT  64      // s-columns per iteration; each warp owns 8
#define NIT  (SK / SKT)
#define KPS  68      // padded stride K private tile / Q tile
#define VPS  72      // padded stride V private tile
#define OSS  65      // padded stride O scratch

#define NTHREADS 256
#define NWARPS   8

// per-warp SMEM block: 2 buffers x (K 8xKPS + V 8xVPS)
#define WKV   (8 * KPS + 8 * VPS)        // 1120 floats per buffer
#define WBLK  (2 * WKV)                  // 2240 floats per warp

__device__ __forceinline__ uint32_t f2tf32(float f) {
    uint32_t u;
    asm("cvt.rna.tf32.f32 %0, %1;" : "=r"(u) : "f"(f));
    return u;
}

__device__ __forceinline__ void mma_tf32(float c[4], const uint32_t a[4], const uint32_t b[2]) {
    asm volatile(
        "mma.sync.aligned.m16n8k8.row.col.f32.tf32.tf32.f32 "
        "{%0,%1,%2,%3}, {%4,%5,%6,%7}, {%8,%9}, {%0,%1,%2,%3};"
        : "+f"(c[0]), "+f"(c[1]), "+f"(c[2]), "+f"(c[3])
        : "r"(a[0]), "r"(a[1]), "r"(a[2]), "r"(a[3]),
          "r"(b[0]), "r"(b[1]));
}

// ---- cp.async helpers ----
__device__ __forceinline__ void cp16(uint32_t smem_dst, const float* gsrc) {
    asm volatile("cp.async.cg.shared.global [%0], [%1], 16;\n"
                 :: "r"(smem_dst), "l"(gsrc));
}
__device__ __forceinline__ void cp_commit() {
    asm volatile("cp.async.commit_group;\n");
}
__device__ __forceinline__ void cp_wait1() {
    asm volatile("cp.async.wait_group 1;\n");
}

// ---- packed f32x2 helpers (FMA-pipe exp path) ----
__device__ __forceinline__ unsigned long long pk2(float a, float b) {
    unsigned long long r;
    asm("mov.b64 %0, {%1,%2};" : "=l"(r) : "f"(a), "f"(b));
    return r;
}
__device__ __forceinline__ void upk2(unsigned long long p, float& a, float& b) {
    asm("mov.b64 {%0,%1}, %2;" : "=f"(a), "=f"(b) : "l"(p));
}
__device__ __forceinline__ unsigned long long fma2(unsigned long long a,
                                                   unsigned long long b,
                                                   unsigned long long c) {
    unsigned long long d;
    asm("fma.rn.f32x2 %0, %1, %2, %3;" : "=l"(d) : "l"(a), "l"(b), "l"(c));
    return d;
}
__device__ __forceinline__ float ex2(float x) {
    float y;
    asm("ex2.approx.f32 %0, %1;" : "=f"(y) : "f"(x));
    return y;
}

// exp(x*0.125) for a pair, entirely on fma+alu pipes (deg-4, rel err ~4e-5).
__device__ __forceinline__ void exp8_pair(float x0, float x1, float& e0, float& e1) {
    const float KKf  = 0.18033688011112042f;   // 0.125 * log2(e)
    const float RNDf = 12582912.0f;            // 2^23 + 2^22
    unsigned long long K2   = pk2(KKf, KKf);
    unsigned long long RND2 = pk2(RNDf, RNDf);
    unsigned long long N1   = pk2(-1.0f, -1.0f);
    unsigned long long C4   = pk2(0.009618127f, 0.009618127f);
    unsigned long long C3   = pk2(0.055504109f, 0.055504109f);
    unsigned long long C2   = pk2(0.240226507f, 0.240226507f);
    unsigned long long C1   = pk2(0.693147181f, 0.693147181f);
    unsigned long long ONE  = pk2(1.0f, 1.0f);

    unsigned long long X = pk2(x0, x1);
    unsigned long long T = fma2(X, K2, RND2);
    unsigned long long W = fma2(T, N1, RND2);
    unsigned long long R = fma2(X, K2, W);
    unsigned long long P = fma2(R, C4, C3);
    P = fma2(P, R, C2);
    P = fma2(P, R, C1);
    P = fma2(P, R, ONE);

    float t0, t1, p0, p1;
    upk2(T, t0, t1);
    upk2(P, p0, p1);
    e0 = __int_as_float(__float_as_int(p0) + (__float_as_int(t0) << 23));
    e1 = __int_as_float(__float_as_int(p1) + (__float_as_int(t1) << 23));
}

__global__ __launch_bounds__(NTHREADS, 2)
void attn_tf32_kernel(const float* __restrict__ q,
                      const float* __restrict__ k,
                      const float* __restrict__ v,
                      float* __restrict__ out) {
    extern __shared__ float sm[];
    const int tid  = threadIdx.x;
    const int lane = tid & 31;
    const int warp = tid >> 5;
    const int gr   = lane >> 2;   // 0..7
    const int tg   = lane & 3;    // 0..3

    // layout: [8 warps x WBLK] | Q[16*KPS] | Os[16*OSS] | red[16] | inv[16]
    float* Wb  = sm + warp * WBLK;             // this warp's double buffer
    float* Qs  = sm + NWARPS * WBLK;
    float* Os  = Qs + 16 * KPS;
    float* red = Os + 16 * OSS;
    float* inv = red + 16;

    const int bh  = blockIdx.y;
    const int q0  = blockIdx.x * BQ;

    const float* qp = q + ((size_t)bh * LQ + q0) * DH;
    const float* kp = k + (size_t)bh * SK * DH;
    const float* vp = v + (size_t)bh * SK * DH;
    float* op = out + ((size_t)bh * LQ + q0) * DH;
    float* sp = out + (size_t)BATCH * HEADS * LQ * DH
                    + ((size_t)bh * LQ + q0) * (size_t)SK;

    // ---- zero scratch ----
    for (int i = tid; i < 16 * OSS; i += NTHREADS) Os[i] = 0.f;
    if (tid < 16) red[tid] = 0.f;

    // ---- load Q tile (16 x 64) : one float4 per thread ----
    {
        int r = tid >> 4, c4 = tid & 15;
        *(float4*)(Qs + r * KPS + c4 * 4) =
            *(const float4*)(qp + (size_t)r * DH + c4 * 4);
    }
    __syncthreads();

    // ---- Q A-fragments (tf32), register-resident ----
    uint32_t qa[8][4];
#pragma unroll
    for (int ks = 0; ks < 8; ks++) {
        qa[ks][0] = f2tf32(Qs[gr * KPS + ks * 8 + tg]);
        qa[ks][1] = f2tf32(Qs[(gr + 8) * KPS + ks * 8 + tg]);
        qa[ks][2] = f2tf32(Qs[gr * KPS + ks * 8 + tg + 4]);
        qa[ks][3] = f2tf32(Qs[(gr + 8) * KPS + ks * 8 + tg + 4]);
    }

    // per-warp O accumulators: 16 rows x 64 cols (8 n-chunks of m16n8)
    float o[8][4];
#pragma unroll
    for (int j = 0; j < 8; j++) { o[j][0] = o[j][1] = o[j][2] = o[j][3] = 0.f; }

    float rs0 = 0.f, rs1 = 0.f;            // row-sum partials (rows gr, gr+8)
    const int wc = warp * 8;               // warp's 8 columns within tile
    const float KKf = 0.18033688011112042f;

    // shuffle source lanes for C-frag -> A-frag redistribution
    const int s1 = (lane & 28) | (tg >> 1);
    const int s2 = s1 + 2;
    const bool odd = (tg & 1);

    const uint32_t wb_sh = (uint32_t)__cvta_generic_to_shared(Wb);

    // stage one (K 8x64, V 8x64) tile into buffer b via cp.async
    auto stage = [&](int b, int s0) {
        uint32_t kd = wb_sh + (uint32_t)(b * WKV) * 4u;
        uint32_t vd = kd + (uint32_t)(8 * KPS) * 4u;
        const float* kpt = kp + (size_t)(s0 + wc) * DH;
        const float* vpt = vp + (size_t)(s0 + wc) * DH;
#pragma unroll
        for (int i = 0; i < 4; i++) {
            int idx = lane + i * 32;
            int r = idx >> 4, c4 = idx & 15;
            cp16(kd + (uint32_t)(r * KPS + c4 * 4) * 4u, kpt + (size_t)r * DH + c4 * 4);
        }
#pragma unroll
        for (int i = 0; i < 4; i++) {
            int idx = lane + i * 32;
            int r = idx >> 4, c4 = idx & 15;
            cp16(vd + (uint32_t)(r * VPS + c4 * 4) * 4u, vpt + (size_t)r * DH + c4 * 4);
        }
    };

    // ==================== barrier-free, double-buffered main loop ====================
    stage(0, 0);
    cp_commit();

#pragma unroll 2
    for (int it = 0; it < NIT; it++) {
        if (it + 1 < NIT) stage((it + 1) & 1, (it + 1) * SKT);
        cp_commit();
        cp_wait1();           // current buffer's group complete
        __syncwarp();

        float* Kw = Wb + (it & 1) * WKV;
        float* Vw = Kw + 8 * KPS;

        // --- QK^T: warp's 8 columns ---
        float acc[4] = {0.f, 0.f, 0.f, 0.f};
#pragma unroll
        for (int ks = 0; ks < 8; ks++) {
            uint32_t b[2];
            b[0] = f2tf32(Kw[gr * KPS + ks * 8 + tg]);
            b[1] = f2tf32(Kw[gr * KPS + ks * 8 + tg + 4]);
            mma_tf32(acc, qa[ks], b);
        }

        // --- exp: pair0 on fma-poly, pair1 on MUFU ---
        float e0, e1, e2, e3;
        exp8_pair(acc[0], acc[1], e0, e1);
        e2 = ex2(acc[2] * KKf);
        e3 = ex2(acc[3] * KKf);

        rs0 += e0 + e1;
        rs1 += e2 + e3;

        // --- write unnormalized scores straight to GMEM ---
        {
            int gcol = it * SKT + wc + 2 * tg;
            *(float2*)(sp + (size_t)gr * SK + gcol)       = make_float2(e0, e1);
            *(float2*)(sp + (size_t)(gr + 8) * SK + gcol) = make_float2(e2, e3);
        }

        // --- C-frag -> A-frag via quad shuffles ---
        uint32_t a0[4];
        {
            float u, w;
            u = __shfl_sync(0xffffffffu, e0, s1);
            w = __shfl_sync(0xffffffffu, e1, s1);
            a0[0] = f2tf32(odd ? w : u);
            u = __shfl_sync(0xffffffffu, e2, s1);
            w = __shfl_sync(0xffffffffu, e3, s1);
            a0[1] = f2tf32(odd ? w : u);
            u = __shfl_sync(0xffffffffu, e0, s2);
            w = __shfl_sync(0xffffffffu, e1, s2);
            a0[2] = f2tf32(odd ? w : u);
            u = __shfl_sync(0xffffffffu, e2, s2);
            w = __shfl_sync(0xffffffffu, e3, s2);
            a0[3] = f2tf32(odd ? w : u);
        }

        // --- PV: O += E_chunk(16x8) @ V(8x64) ---
#pragma unroll
        for (int j = 0; j < 8; j++) {
            uint32_t b[2];
            b[0] = f2tf32(Vw[tg * VPS + j * 8 + gr]);
            b[1] = f2tf32(Vw[(tg + 4) * VPS + j * 8 + gr]);
            mma_tf32(o[j], a0, b);
        }
    }

    // ==================== reductions ====================
    rs0 += __shfl_xor_sync(0xffffffffu, rs0, 1);
    rs0 += __shfl_xor_sync(0xffffffffu, rs0, 2);
    rs1 += __shfl_xor_sync(0xffffffffu, rs1, 1);
    rs1 += __shfl_xor_sync(0xffffffffu, rs1, 2);
    if (tg == 0) {
        atomicAdd(&red[gr], rs0);
        atomicAdd(&red[gr + 8], rs1);
    }
#pragma unroll
    for (int j = 0; j < 8; j++) {
        int c = j * 8 + 2 * tg;
        atomicAdd(&Os[gr * OSS + c],           o[j][0]);
        atomicAdd(&Os[gr * OSS + c + 1],       o[j][1]);
        atomicAdd(&Os[(gr + 8) * OSS + c],     o[j][2]);
        atomicAdd(&Os[(gr + 8) * OSS + c + 1], o[j][3]);
    }
    __syncthreads();
    if (tid < 16) inv[tid] = 1.0f / red[tid];
    __syncthreads();

    // ==================== normalize scores in-place (L2-resident) ====================
    {
#pragma unroll
        for (int i = 0; i < 32; i++) {
            int idx = tid + i * NTHREADS;     // float4 index within 16x2048
            int r  = idx >> 9;                // 512 float4 per row
            int c4 = idx & 511;
            float4 e = *(float4*)(sp + (size_t)r * SK + c4 * 4);
            float is = inv[r];
            e.x *= is; e.y *= is; e.z *= is; e.w *= is;
            *(float4*)(sp + (size_t)r * SK + c4 * 4) = e;
        }
    }

    // ==================== write O ====================
    {
#pragma unroll
        for (int i = 0; i < 4; i++) {
            int idx = tid + i * NTHREADS;     // 0..1023
            int r = idx >> 6, c = idx & 63;
            op[(size_t)r * DH + c] = Os[r * OSS + c] * inv[r];
        }
    }
}

extern "C" void kernel_launch(void* const* d_in, const int* in_sizes, int n_in,
                              void* d_out, int out_size) {
    const float* q = (const float*)d_in[0];
    const float* k = (const float*)d_in[1];
    const float* v = (const float*)d_in[2];
    float* out = (float*)d_out;

    // SMEM (floats): 8*WBLK + 16*KPS + 16*OSS + 32
    size_t smem = (size_t)(NWARPS * WBLK + 16 * KPS + 16 * OSS + 32) * sizeof(float);

    static bool configured = false;
    if (!configured) {
        cudaFuncSetAttribute(attn_tf32_kernel,
                             cudaFuncAttributeMaxDynamicSharedMemorySize,
                             (int)smem);
        configured = true;
    }

    dim3 grid(LQ / BQ, BATCH * HEADS);   // (128, 64)
    attn_tf32_kernel<<<grid, NTHREADS, smem>>>(q, k, v, out);
}

// round 8
// speedup vs baseline: 2.3003x; 1.0576x over previous
#include <cuda_runtime.h>
#include <cstdint>
#include <cstddef>

// Problem constants
#define BATCH 4
#define HEADS 16
#define LQ 2048
#define SK 2048
#define DH 64

// Tiling
#define BQ   32      // query rows per CTA (two 16-row halves, warp-paired)
#define SKT  64      // s-columns per iteration; each PAIR owns 8
#define NIT  (SK / SKT)
#define KPS  68      // padded stride K tile / Q tile
#define VPS  72      // padded stride V tile
#define OSS  65      // padded stride O scratch

#define NTHREADS 512
#define NWARPS   16
#define NPAIRS   8

// per-pair SMEM block: 2 buffers x (K 8xKPS + V 8xVPS)
#define WKV   (8 * KPS + 8 * VPS)        // 1120 floats per buffer
#define WBLK  (2 * WKV)                  // 2240 floats per pair

__device__ __forceinline__ uint32_t f2tf32(float f) {
    uint32_t u;
    asm("cvt.rna.tf32.f32 %0, %1;" : "=r"(u) : "f"(f));
    return u;
}

__device__ __forceinline__ void mma_tf32(float c[4], const uint32_t a[4], const uint32_t b[2]) {
    asm volatile(
        "mma.sync.aligned.m16n8k8.row.col.f32.tf32.tf32.f32 "
        "{%0,%1,%2,%3}, {%4,%5,%6,%7}, {%8,%9}, {%0,%1,%2,%3};"
        : "+f"(c[0]), "+f"(c[1]), "+f"(c[2]), "+f"(c[3])
        : "r"(a[0]), "r"(a[1]), "r"(a[2]), "r"(a[3]),
          "r"(b[0]), "r"(b[1]));
}

// ---- cp.async helpers ----
__device__ __forceinline__ void cp16(uint32_t smem_dst, const float* gsrc) {
    asm volatile("cp.async.cg.shared.global [%0], [%1], 16;\n"
                 :: "r"(smem_dst), "l"(gsrc));
}
__device__ __forceinline__ void cp_commit() {
    asm volatile("cp.async.commit_group;\n");
}
__device__ __forceinline__ void cp_wait1() {
    asm volatile("cp.async.wait_group 1;\n");
}
__device__ __forceinline__ void pair_bar(int id) {
    asm volatile("bar.sync %0, 64;" :: "r"(id) : "memory");
}

// ---- packed f32x2 helpers (FMA-pipe exp path) ----
__device__ __forceinline__ unsigned long long pk2(float a, float b) {
    unsigned long long r;
    asm("mov.b64 %0, {%1,%2};" : "=l"(r) : "f"(a), "f"(b));
    return r;
}
__device__ __forceinline__ void upk2(unsigned long long p, float& a, float& b) {
    asm("mov.b64 {%0,%1}, %2;" : "=f"(a), "=f"(b) : "l"(p));
}
__device__ __forceinline__ unsigned long long fma2(unsigned long long a,
                                                   unsigned long long b,
                                                   unsigned long long c) {
    unsigned long long d;
    asm("fma.rn.f32x2 %0, %1, %2, %3;" : "=l"(d) : "l"(a), "l"(b), "l"(c));
    return d;
}
__device__ __forceinline__ float ex2(float x) {
    float y;
    asm("ex2.approx.f32 %0, %1;" : "=f"(y) : "f"(x));
    return y;
}

// exp(x*0.125) for a pair, entirely on fma+alu pipes (deg-4, rel err ~4e-5).
__device__ __forceinline__ void exp8_pair(float x0, float x1, float& e0, float& e1) {
    const float KKf  = 0.18033688011112042f;   // 0.125 * log2(e)
    const float RNDf = 12582912.0f;            // 2^23 + 2^22
    unsigned long long K2   = pk2(KKf, KKf);
    unsigned long long RND2 = pk2(RNDf, RNDf);
    unsigned long long N1   = pk2(-1.0f, -1.0f);
    unsigned long long C4   = pk2(0.009618127f, 0.009618127f);
    unsigned long long C3   = pk2(0.055504109f, 0.055504109f);
    unsigned long long C2   = pk2(0.240226507f, 0.240226507f);
    unsigned long long C1   = pk2(0.693147181f, 0.693147181f);
    unsigned long long ONE  = pk2(1.0f, 1.0f);

    unsigned long long X = pk2(x0, x1);
    unsigned long long T = fma2(X, K2, RND2);
    unsigned long long W = fma2(T, N1, RND2);
    unsigned long long R = fma2(X, K2, W);
    unsigned long long P = fma2(R, C4, C3);
    P = fma2(P, R, C2);
    P = fma2(P, R, C1);
    P = fma2(P, R, ONE);

    float t0, t1, p0, p1;
    upk2(T, t0, t1);
    upk2(P, p0, p1);
    e0 = __int_as_float(__float_as_int(p0) + (__float_as_int(t0) << 23));
    e1 = __int_as_float(__float_as_int(p1) + (__float_as_int(t1) << 23));
}

__global__ __launch_bounds__(NTHREADS, 1)
void attn_tf32_kernel(const float* __restrict__ q,
                      const float* __restrict__ k,
                      const float* __restrict__ v,
                      float* __restrict__ out) {
    extern __shared__ float sm[];
    const int tid  = threadIdx.x;
    const int lane = tid & 31;
    const int warp = tid >> 5;
    const int pair = warp & 7;       // 0..7
    const int half = warp >> 3;      // 0: rows 0-15, 1: rows 16-31
    const int gr   = lane >> 2;      // 0..7
    const int tg   = lane & 3;       // 0..3

    // layout: [8 pairs x WBLK] | Q[32*KPS] | Os[32*OSS] | red[32] | inv[32]
    float* Pb  = sm + pair * WBLK;             // this pair's double buffer
    float* Qs  = sm + NPAIRS * WBLK;
    float* Os  = Qs + BQ * KPS;
    float* red = Os + BQ * OSS;
    float* inv = red + BQ;

    const int bh  = blockIdx.y;
    const int q0  = blockIdx.x * BQ;

    const float* qp = q + ((size_t)bh * LQ + q0) * DH;
    const float* kp = k + (size_t)bh * SK * DH;
    const float* vp = v + (size_t)bh * SK * DH;
    float* op = out + ((size_t)bh * LQ + q0) * DH;
    float* sp = out + (size_t)BATCH * HEADS * LQ * DH
                    + ((size_t)bh * LQ + q0) * (size_t)SK;

    // ---- zero scratch ----
    for (int i = tid; i < BQ * OSS; i += NTHREADS) Os[i] = 0.f;
    if (tid < BQ) red[tid] = 0.f;

    // ---- load Q tile (32 x 64) : one float4 per thread ----
    {
        int r = tid >> 4, c4 = tid & 15;
        *(float4*)(Qs + r * KPS + c4 * 4) =
            *(const float4*)(qp + (size_t)r * DH + c4 * 4);
    }
    __syncthreads();

    // ---- Q A-fragments for this warp's 16-row half ----
    const int r0 = half * 16;
    uint32_t qa[8][4];
#pragma unroll
    for (int ks = 0; ks < 8; ks++) {
        qa[ks][0] = f2tf32(Qs[(r0 + gr) * KPS + ks * 8 + tg]);
        qa[ks][1] = f2tf32(Qs[(r0 + gr + 8) * KPS + ks * 8 + tg]);
        qa[ks][2] = f2tf32(Qs[(r0 + gr) * KPS + ks * 8 + tg + 4]);
        qa[ks][3] = f2tf32(Qs[(r0 + gr + 8) * KPS + ks * 8 + tg + 4]);
    }

    // per-warp O accumulators: 16 rows x 64 cols (8 n-chunks of m16n8)
    float o[8][4];
#pragma unroll
    for (int j = 0; j < 8; j++) { o[j][0] = o[j][1] = o[j][2] = o[j][3] = 0.f; }

    float rs0 = 0.f, rs1 = 0.f;            // row-sum partials
    const int wc = pair * 8;               // pair's 8 columns within tile
    const float KKf = 0.18033688011112042f;
    const int barid = pair + 1;            // named barriers 1..8 (avoid id 0)

    // shuffle source lanes for C-frag -> A-frag redistribution
    const int s1 = (lane & 28) | (tg >> 1);
    const int s2 = s1 + 2;
    const bool odd = (tg & 1);

    const uint32_t pb_sh = (uint32_t)__cvta_generic_to_shared(Pb);

    // stage one half: half 0 stages K (8x64), half 1 stages V (8x64)
    auto stage = [&](int b, int s0) {
        if (half == 0) {
            uint32_t kd = pb_sh + (uint32_t)(b * WKV) * 4u;
            const float* kpt = kp + (size_t)(s0 + wc) * DH;
#pragma unroll
            for (int i = 0; i < 4; i++) {
                int idx = lane + i * 32;
                int r = idx >> 4, c4 = idx & 15;
                cp16(kd + (uint32_t)(r * KPS + c4 * 4) * 4u, kpt + (size_t)r * DH + c4 * 4);
            }
        } else {
            uint32_t vd = pb_sh + (uint32_t)(b * WKV + 8 * KPS) * 4u;
            const float* vpt = vp + (size_t)(s0 + wc) * DH;
#pragma unroll
            for (int i = 0; i < 4; i++) {
                int idx = lane + i * 32;
                int r = idx >> 4, c4 = idx & 15;
                cp16(vd + (uint32_t)(r * VPS + c4 * 4) * 4u, vpt + (size_t)r * DH + c4 * 4);
            }
        }
    };

    // ==================== pair-synced, double-buffered main loop ====================
    stage(0, 0);
    cp_commit();

#pragma unroll 2
    for (int it = 0; it < NIT; it++) {
        if (it + 1 < NIT) stage((it + 1) & 1, (it + 1) * SKT);
        cp_commit();
        cp_wait1();          // my half of buffer `it` complete
        pair_bar(barid);     // partner's half complete + visible

        float* Kw = Pb + (it & 1) * WKV;
        float* Vw = Kw + 8 * KPS;

        // --- QK^T: pair's 8 columns, this warp's 16 rows ---
        float acc[4] = {0.f, 0.f, 0.f, 0.f};
#pragma unroll
        for (int ks = 0; ks < 8; ks++) {
            uint32_t b[2];
            b[0] = f2tf32(Kw[gr * KPS + ks * 8 + tg]);
            b[1] = f2tf32(Kw[gr * KPS + ks * 8 + tg + 4]);
            mma_tf32(acc, qa[ks], b);
        }

        // --- exp: pair0 on fma-poly, pair1 on MUFU ---
        float e0, e1, e2, e3;
        exp8_pair(acc[0], acc[1], e0, e1);
        e2 = ex2(acc[2] * KKf);
        e3 = ex2(acc[3] * KKf);

        rs0 += e0 + e1;
        rs1 += e2 + e3;

        // --- write unnormalized scores straight to GMEM ---
        {
            int gcol = it * SKT + wc + 2 * tg;
            *(float2*)(sp + (size_t)(r0 + gr) * SK + gcol)     = make_float2(e0, e1);
            *(float2*)(sp + (size_t)(r0 + gr + 8) * SK + gcol) = make_float2(e2, e3);
        }

        // --- C-frag -> A-frag via quad shuffles ---
        uint32_t a0[4];
        {
            float u, w;
            u = __shfl_sync(0xffffffffu, e0, s1);
            w = __shfl_sync(0xffffffffu, e1, s1);
            a0[0] = f2tf32(odd ? w : u);
            u = __shfl_sync(0xffffffffu, e2, s1);
            w = __shfl_sync(0xffffffffu, e3, s1);
            a0[1] = f2tf32(odd ? w : u);
            u = __shfl_sync(0xffffffffu, e0, s2);
            w = __shfl_sync(0xffffffffu, e1, s2);
            a0[2] = f2tf32(odd ? w : u);
            u = __shfl_sync(0xffffffffu, e2, s2);
            w = __shfl_sync(0xffffffffu, e3, s2);
            a0[3] = f2tf32(odd ? w : u);
        }

        // --- PV: O += E_chunk(16x8) @ V(8x64) ---
#pragma unroll
        for (int j = 0; j < 8; j++) {
            uint32_t b[2];
            b[0] = f2tf32(Vw[tg * VPS + j * 8 + gr]);
            b[1] = f2tf32(Vw[(tg + 4) * VPS + j * 8 + gr]);
            mma_tf32(o[j], a0, b);
        }

        pair_bar(barid);     // partner done reading buffer `it` (WAR for next stage)
    }

    // ==================== reductions ====================
    rs0 += __shfl_xor_sync(0xffffffffu, rs0, 1);
    rs0 += __shfl_xor_sync(0xffffffffu, rs0, 2);
    rs1 += __shfl_xor_sync(0xffffffffu, rs1, 1);
    rs1 += __shfl_xor_sync(0xffffffffu, rs1, 2);
    if (tg == 0) {
        atomicAdd(&red[r0 + gr], rs0);
        atomicAdd(&red[r0 + gr + 8], rs1);
    }
#pragma unroll
    for (int j = 0; j < 8; j++) {
        int c = j * 8 + 2 * tg;
        atomicAdd(&Os[(r0 + gr) * OSS + c],           o[j][0]);
        atomicAdd(&Os[(r0 + gr) * OSS + c + 1],       o[j][1]);
        atomicAdd(&Os[(r0 + gr + 8) * OSS + c],       o[j][2]);
        atomicAdd(&Os[(r0 + gr + 8) * OSS + c + 1],   o[j][3]);
    }
    __syncthreads();
    if (tid < BQ) inv[tid] = 1.0f / red[tid];
    __syncthreads();

    // ==================== normalize scores in-place (L2-resident) ====================
    {
#pragma unroll
        for (int i = 0; i < 32; i++) {
            int idx = tid + i * NTHREADS;     // float4 index within 32x2048
            int r  = idx >> 9;                // 512 float4 per row
            int c4 = idx & 511;
            float4 e = *(float4*)(sp + (size_t)r * SK + c4 * 4);
            float is = inv[r];
            e.x *= is; e.y *= is; e.z *= is; e.w *= is;
            *(float4*)(sp + (size_t)r * SK + c4 * 4) = e;
        }
    }

    // ==================== write O ====================
    {
#pragma unroll
        for (int i = 0; i < 4; i++) {
            int idx = tid + i * NTHREADS;     // 0..2047
            int r = idx >> 6, c = idx & 63;
            op[(size_t)r * DH + c] = Os[r * OSS + c] * inv[r];
        }
    }
}

extern "C" void kernel_launch(void* const* d_in, const int* in_sizes, int n_in,
                              void* d_out, int out_size) {
    const float* q = (const float*)d_in[0];
    const float* k = (const float*)d_in[1];
    const float* v = (const float*)d_in[2];
    float* out = (float*)d_out;

    // SMEM (floats): 8*WBLK + 32*KPS + 32*OSS + 64
    size_t smem = (size_t)(NPAIRS * WBLK + BQ * KPS + BQ * OSS + 2 * BQ) * sizeof(float);

    static bool configured = false;
    if (!configured) {
        cudaFuncSetAttribute(attn_tf32_kernel,
                             cudaFuncAttributeMaxDynamicSharedMemorySize,
                             (int)smem);
        configured = true;
    }

    dim3 grid(LQ / BQ, BATCH * HEADS);   // (64, 64)
    attn_tf32_kernel<<<grid, NTHREADS, smem>>>(q, k, v, out);
}